// round 6
// baseline (speedup 1.0000x reference)
#include <cuda_runtime.h>
#include <cuda_bf16.h>
#include <cstdint>

#define FULL_MASK 0xFFFFFFFFu

constexpr int E_EDGES = 65536;
constexpr int F_DIM   = 128;
constexpr int D_DEG   = 32;
constexpr int EPB     = 32;              // edges per block
constexpr int THREADS = 256;

__device__ __forceinline__ void cp_async16(uint32_t smem_dst, const void* gsrc) {
    asm volatile("cp.async.cg.shared.global [%0], [%1], 16;" :: "r"(smem_dst), "l"(gsrc));
}
__device__ __forceinline__ void cp_async_commit_wait_all() {
    asm volatile("cp.async.commit_group;\n\tcp.async.wait_group 0;" ::: "memory");
}

// Block-staged gather: each block stages 32 edges' feature rows + neighbor rows
// into smem via cp.async (high MLP, no register cost), then 8 warps compute
// 4 edges each from smem.
// out[e] = sum_f xi[f]*xj[f]*W[f] + sum_{d: ni[d] in nj} dot(x[ni[d]], W[F:2F]) + b
__global__ void __launch_bounds__(THREADS)
ncn_kernel(const float* __restrict__ x,
           const int*   __restrict__ nbr,
           const int*   __restrict__ tar_ei,
           const float* __restrict__ W,
           const float* __restrict__ b,
           float*       __restrict__ out)
{
    __shared__ __align__(16) float xs[2 * EPB * F_DIM];  // 32KB: rows 0..31 = src rows, 32..63 = dst rows
    __shared__ __align__(16) int   nb[2 * EPB * D_DEG];  // 8KB : same row convention
    __shared__ int idx[2 * EPB];

    const int tid  = threadIdx.x;
    const int lane = tid & 31;
    const int wid  = tid >> 5;
    const int e0   = blockIdx.x * EPB;

    // Stage edge indices: idx[0:32] = srcs, idx[32:64] = dsts.
    if (tid < EPB)           idx[tid] = __ldg(tar_ei + e0 + tid);
    else if (tid < 2 * EPB)  idx[tid] = __ldg(tar_ei + E_EDGES + e0 + (tid - EPB));
    __syncthreads();

    // Stage 64 feature rows (512B each): 2048 16B-chunks, 8 per thread, all independent.
    {
        const uint32_t xs_base = (uint32_t)__cvta_generic_to_shared(xs);
        #pragma unroll
        for (int c = tid; c < 2 * EPB * (F_DIM / 4); c += THREADS) {
            const int r = c >> 5;            // row 0..63
            const int o = c & 31;            // 16B chunk within row
            cp_async16(xs_base + (uint32_t)(r * F_DIM + o * 4) * 4,
                       x + (size_t)idx[r] * F_DIM + o * 4);
        }
    }
    // Stage 64 neighbor rows (128B each): 512 16B-chunks, 2 per thread.
    {
        const uint32_t nb_base = (uint32_t)__cvta_generic_to_shared(nb);
        #pragma unroll
        for (int c = tid; c < 2 * EPB * (D_DEG / 4); c += THREADS) {
            const int r = c >> 3;
            const int o = c & 7;
            cp_async16(nb_base + (uint32_t)(r * D_DEG + o * 4) * 4,
                       nbr + (size_t)idx[r] * D_DEG + o * 4);
        }
    }

    // Weights (L2-resident after first touch) while copies are in flight.
    const float4 w0 = __ldg(&reinterpret_cast<const float4*>(W)[lane]);
    const float4 w1 = __ldg(&reinterpret_cast<const float4*>(W + F_DIM)[lane]);
    const float  bv = __ldg(b);

    cp_async_commit_wait_all();
    __syncthreads();

    const float4* xv = reinterpret_cast<const float4*>(x);

    // Each warp computes 4 edges from smem.
    #pragma unroll
    for (int q = 0; q < EPB / 8; ++q) {
        const int k = wid * (EPB / 8) + q;   // edge slot 0..31

        const float4 a = reinterpret_cast<const float4*>(xs + k * F_DIM)[lane];
        const float4 c = reinterpret_cast<const float4*>(xs + (EPB + k) * F_DIM)[lane];
        const int ni_l = nb[k * D_DEG + lane];
        const int nj_l = nb[(EPB + k) * D_DEG + lane];

        float acc = a.x*c.x*w0.x + a.y*c.y*w0.y + a.z*c.z*w0.z + a.w*c.w*w0.w;

        // lower_bound of ni_l in sorted distributed nj (clip + equality,
        // matching jnp.searchsorted semantics).
        int lo = 0, hi = D_DEG - 1;
        #pragma unroll
        for (int s = 0; s < 5; ++s) {
            const int mid = (lo + hi) >> 1;
            const int v   = __shfl_sync(FULL_MASK, nj_l, mid);
            if (v < ni_l) lo = mid + 1; else hi = mid;
        }
        const bool hit = (__shfl_sync(FULL_MASK, nj_l, lo) == ni_l);

        // Rare common-neighbor contributions (warp-uniform mask).
        unsigned hm = __ballot_sync(FULL_MASK, hit);
        while (hm) {
            const int h = __ffs(hm) - 1; hm &= hm - 1u;
            const int cn = __shfl_sync(FULL_MASK, ni_l, h);
            const float4 xc = __ldg(&xv[(size_t)cn * (F_DIM / 4) + lane]);
            acc += xc.x*w1.x + xc.y*w1.y + xc.z*w1.z + xc.w*w1.w;
        }

        #pragma unroll
        for (int off = 16; off >= 1; off >>= 1)
            acc += __shfl_down_sync(FULL_MASK, acc, off);

        if (lane == 0) out[e0 + k] = acc + bv;
    }
}

extern "C" void kernel_launch(void* const* d_in, const int* in_sizes, int n_in,
                              void* d_out, int out_size)
{
    const float* x      = (const float*)d_in[0];
    const int*   nbr    = (const int*)  d_in[1];
    const int*   tar_ei = (const int*)  d_in[2];
    const float* W      = (const float*)d_in[3];
    const float* b      = (const float*)d_in[4];
    float*       out    = (float*)d_out;

    // 65536 edges / 32 per block = 2048 blocks, 256 threads each.
    ncn_kernel<<<E_EDGES / EPB, THREADS>>>(x, nbr, tar_ei, W, b, out);
}

// round 9
// speedup vs baseline: 1.1322x; 1.1322x over previous
#include <cuda_runtime.h>
#include <cuda_bf16.h>
#include <cstdint>

#define FULL_MASK 0xFFFFFFFFu

constexpr int E_EDGES = 65536;
constexpr int F_DIM   = 128;
constexpr int D_DEG   = 32;
constexpr int BLOCKS  = 740;       // 148 SMs x 5 resident blocks = one wave
constexpr int THREADS = 256;
constexpr int N_WARPS = BLOCKS * (THREADS / 32);   // 5920 warps, ~11 edges each

// One warp per edge, grid-stride, 2-stage software pipeline:
//   idx prefetched at distance 2, rows (x + nbr) prefetched at distance 1,
//   so edge k's shuffle-heavy compute overlaps edge k+1's gathers in-warp.
// out[e] = sum_f xi[f]*xj[f]*W[f] + sum_{d: ni[d] in nj} dot(x[ni[d]], W[F:2F]) + b
__global__ void __launch_bounds__(THREADS, 5)
ncn_kernel(const float* __restrict__ x,
           const int*   __restrict__ nbr,
           const int*   __restrict__ tar_ei,
           const float* __restrict__ W,
           const float* __restrict__ b,
           float*       __restrict__ out)
{
    const int lane = threadIdx.x & 31;
    const int w    = (blockIdx.x * blockDim.x + threadIdx.x) >> 5;

    const float4* xv = reinterpret_cast<const float4*>(x);

    // Per-lane weight slices (W is [256,1]): W0 = W[0:128], W1 = W[128:256]
    const float4 w0 = __ldg(&reinterpret_cast<const float4*>(W)[lane]);
    const float4 w1 = __ldg(&reinterpret_cast<const float4*>(W + F_DIM)[lane]);
    const float  bv = __ldg(b);

    // ---- pipeline prologue ----
    int e = w;                                   // current edge
    if (e >= E_EDGES) return;                    // (never true at this config)

    // idx for current (lane-invariant broadcast loads)
    int i_c = __ldg(tar_ei + e);
    int j_c = __ldg(tar_ei + E_EDGES + e);

    // idx for next (clamped so loads stay in-bounds on the tail)
    int e1        = e + N_WARPS;
    const int ec1 = min(e1, E_EDGES - 1);
    int i_n = __ldg(tar_ei + ec1);
    int j_n = __ldg(tar_ei + E_EDGES + ec1);

    // rows for current
    float4 a_c = __ldg(&xv[(size_t)i_c * (F_DIM/4) + lane]);
    float4 c_c = __ldg(&xv[(size_t)j_c * (F_DIM/4) + lane]);
    int   ni_c = __ldg(nbr + (size_t)i_c * D_DEG + lane);
    int   nj_c = __ldg(nbr + (size_t)j_c * D_DEG + lane);

    while (true) {
        // ---- stage: issue next edge's row gathers (overlap with compute below) ----
        const float4 a_n = __ldg(&xv[(size_t)i_n * (F_DIM/4) + lane]);
        const float4 c_n = __ldg(&xv[(size_t)j_n * (F_DIM/4) + lane]);
        const int   ni_n = __ldg(nbr + (size_t)i_n * D_DEG + lane);
        const int   nj_n = __ldg(nbr + (size_t)j_n * D_DEG + lane);

        // ---- stage: issue idx for edge after next ----
        const int e2  = e1 + N_WARPS;
        const int ec2 = min(e2, E_EDGES - 1);
        const int i_n2 = __ldg(tar_ei + ec2);
        const int j_n2 = __ldg(tar_ei + E_EDGES + ec2);

        // ---- compute current edge (rows already resident) ----
        float acc = a_c.x*c_c.x*w0.x + a_c.y*c_c.y*w0.y
                  + a_c.z*c_c.z*w0.z + a_c.w*c_c.w*w0.w;

        // lower_bound of ni_c in sorted distributed nj_c (clip + equality,
        // matching jnp.searchsorted semantics in the reference).
        int lo = 0, hi = D_DEG - 1;
        #pragma unroll
        for (int s = 0; s < 5; ++s) {
            const int mid = (lo + hi) >> 1;
            const int v   = __shfl_sync(FULL_MASK, nj_c, mid);
            if (v < ni_c) lo = mid + 1; else hi = mid;
        }
        const bool hit = (__shfl_sync(FULL_MASK, nj_c, lo) == ni_c);

        // Rare common-neighbor contributions (warp-uniform mask keeps convergence).
        unsigned hm = __ballot_sync(FULL_MASK, hit);
        while (hm) {
            const int h = __ffs(hm) - 1; hm &= hm - 1u;
            const int cn = __shfl_sync(FULL_MASK, ni_c, h);
            const float4 xc = __ldg(&xv[(size_t)cn * (F_DIM/4) + lane]);
            acc += xc.x*w1.x + xc.y*w1.y + xc.z*w1.z + xc.w*w1.w;
        }

        // Warp reduction (butterfly; plain-sm_100 safe, no redux.f32 here).
        #pragma unroll
        for (int off = 16; off >= 1; off >>= 1)
            acc += __shfl_down_sync(FULL_MASK, acc, off);

        if (lane == 0) out[e] = acc + bv;

        // ---- rotate pipeline ----
        if (e1 >= E_EDGES) break;
        e   = e1;  e1  = e2;
        a_c = a_n; c_c = c_n; ni_c = ni_n; nj_c = nj_n;
        i_n = i_n2; j_n = j_n2;
    }
}

extern "C" void kernel_launch(void* const* d_in, const int* in_sizes, int n_in,
                              void* d_out, int out_size)
{
    const float* x      = (const float*)d_in[0];
    const int*   nbr    = (const int*)  d_in[1];
    const int*   tar_ei = (const int*)  d_in[2];
    const float* W      = (const float*)d_in[3];
    const float* b      = (const float*)d_in[4];
    float*       out    = (float*)d_out;

    ncn_kernel<<<BLOCKS, THREADS>>>(x, nbr, tar_ei, W, b, out);
}